// round 6
// baseline (speedup 1.0000x reference)
#include <cuda_runtime.h>
#include <cuda_bf16.h>

#define NQ    18
#define NBAT  16

typedef unsigned long long u64;

// ---- f32x2 packed helpers (sm_103a FFMA2 path; only reachable via PTX) ----
__device__ __forceinline__ u64 pk(float lo, float hi) {
    u64 r; asm("mov.b64 %0,{%1,%2};" : "=l"(r) : "f"(lo), "f"(hi)); return r;
}
__device__ __forceinline__ void upk(u64 v, float& lo, float& hi) {
    asm("mov.b64 {%0,%1},%2;" : "=f"(lo), "=f"(hi) : "l"(v));
}
__device__ __forceinline__ u64 fma2(u64 a, u64 b, u64 c) {
    u64 d; asm("fma.rn.f32x2 %0,%1,%2,%3;" : "=l"(d) : "l"(a), "l"(b), "l"(c)); return d;
}
__device__ __forceinline__ u64 mul2(u64 a, u64 b) {
    u64 d; asm("mul.rn.f32x2 %0,%1,%2;" : "=l"(d) : "l"(a), "l"(b)); return d;
}
__device__ __forceinline__ u64 add2(u64 a, u64 b) {
    u64 d; asm("add.rn.f32x2 %0,%1,%2;" : "=l"(d) : "l"(a), "l"(b)); return d;
}

// Bond state s = (w<<2)|(y<<1)|y', packed as pairs P[j] = (2j, 2j+1).
// Site op = A(bit1)*B(bit0)*C(bit2); all stages symmetric so the transpose
// sweep is the same formulas in reverse order (C, A, B).

// stride-5 u64 per (site,batch): 40B/lane keeps 16 lanes conflict-free
__shared__ u64 g_cst[NQ][NBAT][5];
__shared__ u64 g_sL [NQ][NBAT][5];
__shared__ u64 g_sS [NQ][NBAT][5];

__global__ void __launch_bounds__(128, 1)
quantum_mps_kernel(const float* __restrict__ in, float* __restrict__ out) {
    const int tid = threadIdx.x;
    const int wid = tid >> 5;
    const int b   = tid & 31;
    const bool active = (b < NBAT);

    // ---- phase 1: ALL threads produce coefficients (batch-major mapping).
    // Thread t < 96 owns pairs p = 3t..3t+2; same batch (18 % 3 == 0), so its
    // 6 global loads are consecutive -> near-coalesced; 12 MUFU per thread.
    if (tid < 96) {
        const int pb = tid / 6;            // batch
        const int s0 = 3 * (tid % 6);      // first site of this thread
        const float* a0 = in + pb * (2 * NQ) + s0;        // layer 0
        const float* a1 = a0 + NQ;                        // layer 1
        #pragma unroll
        for (int j = 0; j < 3; j++) {
            const int s = s0 + j;
            float c0, sn0, c1, sn1;
            __sincosf(0.5f * a0[j], &sn0, &c0);
            __sincosf(0.5f * a1[j], &sn1, &c1);
            const float cc = c1 * c1, ss = sn1 * sn1, cs = c1 * sn1, ncs = -cs;
            g_cst[s][pb][0] = pk(c0,  sn0);
            g_cst[s][pb][1] = pk(cc,  ncs);   // r0, even pairs
            g_cst[s][pb][2] = pk(ncs, ss);    // r0, odd pairs
            g_cst[s][pb][3] = pk(ss,  cs);    // r1, even pairs
            g_cst[s][pb][4] = pk(cs,  cc);    // r1, odd pairs
        }
    }
    __syncthreads();

    // ---- phase 2: warp 0 forward sweep, warp 1 backward sweep ----
    if (active && wid == 0) {
        u64 P0 = pk(1.f, 0.f), P1 = pk(0.f, 0.f), P2 = P1, P3 = P1;
        #pragma unroll
        for (int i = 0; i < NQ; i++) {
            const u64 k0  = g_cst[i][b][0];
            const u64 r0e = g_cst[i][b][1], r0o = g_cst[i][b][2];
            const u64 r1e = g_cst[i][b][3], r1o = g_cst[i][b][4];
            float C0, S0; upk(k0, C0, S0);
            const u64 C0p = pk(C0, C0), S0p = pk(S0, S0);
            // A (packed, partner j^1)
            const u64 T0 = fma2(C0p, P0, mul2(S0p, P1));
            const u64 T1 = fma2(C0p, P1, mul2(S0p, P0));
            const u64 T2 = fma2(C0p, P2, mul2(S0p, P3));
            const u64 T3 = fma2(C0p, P3, mul2(S0p, P2));
            // B (scalar, intra-pair)
            float t0,t1,t2,t3,t4,t5,t6,t7;
            upk(T0,t0,t1); upk(T1,t2,t3); upk(T2,t4,t5); upk(T3,t6,t7);
            const u64 V0 = pk(fmaf(C0,t0,S0*t1), fmaf(C0,t1,S0*t0));
            const u64 V1 = pk(fmaf(C0,t2,S0*t3), fmaf(C0,t3,S0*t2));
            const u64 V2 = pk(fmaf(C0,t4,S0*t5), fmaf(C0,t5,S0*t4));
            const u64 V3 = pk(fmaf(C0,t6,S0*t7), fmaf(C0,t7,S0*t6));
            // C (packed, partner j^2)
            P0 = fma2(r0e, V0, mul2(r1e, V2));
            P1 = fma2(r0o, V1, mul2(r1o, V3));
            P2 = fma2(r0e, V2, mul2(r1e, V0));
            P3 = fma2(r0o, V3, mul2(r1o, V1));
            g_sL[i][b][0] = P0; g_sL[i][b][1] = P1;
            g_sL[i][b][2] = P2; g_sL[i][b][3] = P3;
        }
    } else if (active && wid == 1) {
        u64 U0 = pk(1.f, 1.f), U1 = U0, U2 = U0, U3 = U0;
        g_sS[NQ-1][b][0] = U0; g_sS[NQ-1][b][1] = U1;
        g_sS[NQ-1][b][2] = U2; g_sS[NQ-1][b][3] = U3;
        #pragma unroll
        for (int k = NQ - 2; k >= 0; k--) {
            const int i = k + 1;
            const u64 k0  = g_cst[i][b][0];
            const u64 r0e = g_cst[i][b][1], r0o = g_cst[i][b][2];
            const u64 r1e = g_cst[i][b][3], r1o = g_cst[i][b][4];
            float C0, S0; upk(k0, C0, S0);
            const u64 C0p = pk(C0, C0), S0p = pk(S0, S0);
            // C^T = C (packed)
            const u64 T0 = fma2(r0e, U0, mul2(r1e, U2));
            const u64 T1 = fma2(r0o, U1, mul2(r1o, U3));
            const u64 T2 = fma2(r0e, U2, mul2(r1e, U0));
            const u64 T3 = fma2(r0o, U3, mul2(r1o, U1));
            // A (packed)
            const u64 W0 = fma2(C0p, T0, mul2(S0p, T1));
            const u64 W1 = fma2(C0p, T1, mul2(S0p, T0));
            const u64 W2 = fma2(C0p, T2, mul2(S0p, T3));
            const u64 W3 = fma2(C0p, T3, mul2(S0p, T2));
            // B (scalar) + repack
            float w0,w1,w2,w3,w4,w5,w6,w7;
            upk(W0,w0,w1); upk(W1,w2,w3); upk(W2,w4,w5); upk(W3,w6,w7);
            U0 = pk(fmaf(C0,w0,S0*w1), fmaf(C0,w1,S0*w0));
            U1 = pk(fmaf(C0,w2,S0*w3), fmaf(C0,w3,S0*w2));
            U2 = pk(fmaf(C0,w4,S0*w5), fmaf(C0,w5,S0*w4));
            U3 = pk(fmaf(C0,w6,S0*w7), fmaf(C0,w7,S0*w6));
            g_sS[k][b][0] = U0; g_sS[k][b][1] = U1;
            g_sS[k][b][2] = U2; g_sS[k][b][3] = U3;
        }
    }
    __syncthreads();

    // ---- phase 3: readout split 5/5/4/4 across all warps ----
    if (active) {
        const int st = (wid < 2) ? wid * 5 : 10 + (wid - 2) * 4;
        const int en = st + ((wid < 2) ? 5 : 4);
        #pragma unroll
        for (int i = st; i < en; i++) {
            const u64 M0 = mul2(g_sL[i][b][0], g_sS[i][b][0]);
            const u64 M1 = mul2(g_sL[i][b][1], g_sS[i][b][1]);
            const u64 M2 = mul2(g_sL[i][b][2], g_sS[i][b][2]);   // w=1
            const u64 M3 = mul2(g_sL[i][b][3], g_sS[i][b][3]);   // w=1
            const u64 Ap = add2(M0, M1);
            const u64 An = add2(M2, M3);
            float pl, ph, nl, nh;
            upk(Ap, pl, ph); upk(An, nl, nh);
            out[b * NQ + i] = (pl + ph) - (nl + nh);
        }
    }
}

extern "C" void kernel_launch(void* const* d_in, const int* in_sizes, int n_in,
                              void* d_out, int out_size) {
    const float* in  = (const float*)d_in[0];
    float*       out = (float*)d_out;
    quantum_mps_kernel<<<1, 128>>>(in, out);
}